// round 6
// baseline (speedup 1.0000x reference)
#include <cuda_runtime.h>
#include <cstdint>

// YOLO loss, fused single kernel: warp-private 3-deep TMA pipelines.
// Each warp owns 3 smem stages (32 cells each) + 3 mbarriers and streams its
// own chunk sequence with no block-level synchronization in the main loop.

#define THREADS    128
#define WARPS      4
#define CHUNK      32
#define STAGES     3
#define NPART_MAX  2048

#define CH_P_BYTES  (CHUNK * 30 * 4)                    // 3840
#define CH_C_BYTES  (CHUNK * 4)                         // 128
#define STAGE_BYTES (2 * CH_P_BYTES + CH_C_BYTES)       // 7808 (16B multiple)
#define STAGE_TX    STAGE_BYTES
#define WARP_SMEM   (STAGES * STAGE_BYTES)              // 23424
#define SMEM_DYN    (WARPS * WARP_SMEM)                 // 93696

__device__ float        g_part[6][NPART_MAX];
__device__ unsigned int g_count = 0;

__device__ __forceinline__ uint32_t smem_u32(const void* p)
{
    return (uint32_t)__cvta_generic_to_shared(p);
}
__device__ __forceinline__ void mbar_init(uint32_t mbar, uint32_t count)
{
    asm volatile("mbarrier.init.shared.b64 [%0], %1;" :: "r"(mbar), "r"(count) : "memory");
}
__device__ __forceinline__ void mbar_expect_tx(uint32_t mbar, uint32_t bytes)
{
    asm volatile("mbarrier.arrive.expect_tx.shared.b64 _, [%0], %1;"
                 :: "r"(mbar), "r"(bytes) : "memory");
}
__device__ __forceinline__ void bulk_g2s(uint32_t smem_dst, const void* gmem_src,
                                         uint32_t bytes, uint32_t mbar)
{
    asm volatile("cp.async.bulk.shared::cta.global.mbarrier::complete_tx::bytes "
                 "[%0], [%1], %2, [%3];"
                 :: "r"(smem_dst), "l"(gmem_src), "r"(bytes), "r"(mbar) : "memory");
}
__device__ __forceinline__ void fence_proxy_async_shared()
{
    asm volatile("fence.proxy.async.shared::cta;" ::: "memory");
}
__device__ __forceinline__ void mbar_wait(uint32_t mbar, uint32_t parity)
{
    asm volatile(
        "{\n\t"
        ".reg .pred P;\n\t"
        "WAIT_%=:\n\t"
        "mbarrier.try_wait.parity.acquire.cta.shared::cta.b64 P, [%0], %1, 0x989680;\n\t"
        "@P bra DONE_%=;\n\t"
        "bra WAIT_%=;\n\t"
        "DONE_%=:\n\t"
        "}"
        :: "r"(mbar), "r"(parity) : "memory");
}

// per-cell loss; acc[6] = {loc, cls, obj, noobj, m, nm}
__device__ __forceinline__ void cell_compute(const float* __restrict__ p,
                                             const float* __restrict__ t,
                                             bool c, float acc[6])
{
    const int o = c ? 0 : 5;
    const float tconf = t[4];

    if (tconf > 0.f) {
        acc[4] += 1.f;
        float dx = p[o + 0] - t[o + 0];
        float dy = p[o + 1] - t[o + 1];
        float dw = p[o + 2] - sqrtf(t[o + 2]);
        float dh = p[o + 3] - sqrtf(t[o + 3]);
        acc[0] += 0.5f * (dx * dx + dy * dy) + 0.5f * (dw * dw + dh * dh);
        float tobj = c ? tconf : t[9];
        float d = p[o + 4] - tobj;
        acc[2] += d * d;
        // ce = log(sum(exp(sm))) - sm[argmax(tcls)], sm = softmax(logits).
        // sm in [0,1] -> shiftless second LSE is numerically safe.
        float mx = -1e30f;
        #pragma unroll
        for (int k = 0; k < 20; k++) mx = fmaxf(mx, p[10 + k]);
        float sm[20];
        float den = 0.f;
        #pragma unroll
        for (int k = 0; k < 20; k++) { sm[k] = __expf(p[10 + k] - mx); den += sm[k]; }
        float inv = __fdividef(1.f, den);
        float den2 = 0.f;
        #pragma unroll
        for (int k = 0; k < 20; k++) { sm[k] *= inv; den2 += __expf(sm[k]); }
        float lse2 = __logf(den2);
        float bm = t[10]; int bi = 0;
        #pragma unroll
        for (int k = 1; k < 20; k++) { float v = t[10 + k]; if (v > bm) { bm = v; bi = k; } }
        acc[1] += lse2 - sm[bi];
    } else {
        acc[5] += 1.f;
        float d0 = p[4] - tconf;
        float d1 = p[9] - t[9];
        acc[3] += d0 * d0 + d1 * d1;
    }
}

__device__ __forceinline__ void block_reduce6(float* vals, float* s_red, int tid)
{
    #pragma unroll
    for (int v = 0; v < 6; v++) {
        #pragma unroll
        for (int off = 16; off > 0; off >>= 1)
            vals[v] += __shfl_down_sync(0xffffffffu, vals[v], off);
    }
    const int warp = tid >> 5;
    const int lane = tid & 31;
    if (lane == 0) {
        #pragma unroll
        for (int v = 0; v < 6; v++) s_red[warp * 6 + v] = vals[v];
    }
    __syncthreads();
    if (tid == 0) {
        #pragma unroll
        for (int v = 0; v < 6; v++)
            vals[v] = s_red[v] + s_red[6 + v] + s_red[12 + v] + s_red[18 + v];
    }
}

__global__ __launch_bounds__(THREADS)
void yolo_fused(const float* __restrict__ pred,
                const float* __restrict__ target,
                const int*   __restrict__ choice,
                float*       __restrict__ out,
                int n_cells)
{
    extern __shared__ __align__(16) char dynsmem[];
    __shared__ __align__(8) unsigned long long mbar_mem[WARPS * STAGES];
    __shared__ float s_red[4 * 6];
    __shared__ bool  s_last;

    const int tid  = threadIdx.x;
    const int wid  = tid >> 5;
    const int lane = tid & 31;

    char* wbase = dynsmem + wid * WARP_SMEM;
    uint32_t mb[STAGES];
    #pragma unroll
    for (int s = 0; s < STAGES; s++)
        mb[s] = smem_u32(&mbar_mem[wid * STAGES + s]);

    if (tid < WARPS * STAGES) mbar_init(smem_u32(&mbar_mem[tid]), 1);
    __syncthreads();

    const long long w  = (long long)blockIdx.x * WARPS + wid;   // global warp id
    const long long NW = (long long)gridDim.x * WARPS;
    const long long n_chunks = n_cells / CHUNK;

    // ---- prologue: fill all 3 stages ----
    if (lane == 0) {
        #pragma unroll
        for (int s = 0; s < STAGES; s++) {
            long long ch = w + (long long)s * NW;
            if (ch < n_chunks) {
                char* sb = wbase + s * STAGE_BYTES;
                mbar_expect_tx(mb[s], STAGE_TX);
                bulk_g2s(smem_u32(sb),               pred   + ch * CHUNK * 30, CH_P_BYTES, mb[s]);
                bulk_g2s(smem_u32(sb + CH_P_BYTES),  target + ch * CHUNK * 30, CH_P_BYTES, mb[s]);
                bulk_g2s(smem_u32(sb + 2*CH_P_BYTES), choice + ch * CHUNK,     CH_C_BYTES, mb[s]);
            }
        }
    }

    float acc[6] = {0.f, 0.f, 0.f, 0.f, 0.f, 0.f};
    uint32_t ph[STAGES] = {0u, 0u, 0u};

    int s = 0;
    for (long long ch = w; ch < n_chunks; ch += NW) {
        mbar_wait(mb[s], ph[s]);
        ph[s] ^= 1u;

        char* sb = wbase + s * STAGE_BYTES;
        const float* sp = (const float*)sb;
        const float* st = (const float*)(sb + CH_P_BYTES);
        const int*   sc = (const int*)  (sb + 2 * CH_P_BYTES);

        cell_compute(sp + lane * 30, st + lane * 30, sc[lane] != 0, acc);

        __syncwarp();                         // all lanes done reading stage s

        long long nch = ch + (long long)STAGES * NW;
        if (lane == 0 && nch < n_chunks) {
            fence_proxy_async_shared();       // order generic reads before async writes
            mbar_expect_tx(mb[s], STAGE_TX);
            bulk_g2s(smem_u32(sb),               pred   + nch * CHUNK * 30, CH_P_BYTES, mb[s]);
            bulk_g2s(smem_u32(sb + CH_P_BYTES),  target + nch * CHUNK * 30, CH_P_BYTES, mb[s]);
            bulk_g2s(smem_u32(sb + 2*CH_P_BYTES), choice + nch * CHUNK,     CH_C_BYTES, mb[s]);
        }
        s = (s + 1 == STAGES) ? 0 : s + 1;
    }

    // tail cells (n_cells % 32, zero for this shape): global warp 0, direct
    if (w == 0) {
        for (long long cell = n_chunks * CHUNK + lane; cell < n_cells; cell += 32)
            cell_compute(pred + cell * 30, target + cell * 30, choice[cell] != 0, acc);
    }

    __syncthreads();
    block_reduce6(acc, s_red, tid);

    if (tid == 0) {
        #pragma unroll
        for (int v = 0; v < 6; v++) g_part[v][blockIdx.x] = acc[v];
        __threadfence();
        unsigned int ticket = atomicAdd(&g_count, 1u);
        s_last = (ticket == gridDim.x - 1);
    }
    __syncthreads();

    if (s_last) {
        __threadfence();
        const int npart = gridDim.x;
        float a[6] = {0.f, 0.f, 0.f, 0.f, 0.f, 0.f};
        for (int i = tid; i < npart; i += THREADS) {
            #pragma unroll
            for (int v = 0; v < 6; v++) a[v] += g_part[v][i];
        }
        __syncthreads();
        block_reduce6(a, s_red, tid);
        if (tid == 0) {
            float n_obj = fmaxf(a[4], 1.f);
            float n_no  = fmaxf(a[5], 1.f);
            out[0] = 5.0f * a[0];
            out[1] = a[1] / n_obj;
            out[2] = a[2];
            out[3] = 0.5f * a[3] / n_no;
            g_count = 0;   // reset for next graph replay
        }
    }
}

extern "C" void kernel_launch(void* const* d_in, const int* in_sizes, int n_in,
                              void* d_out, int out_size)
{
    const float* pred   = (const float*)d_in[0];
    const float* target = (const float*)d_in[1];
    const int*   choice = (const int*)d_in[2];
    float* out = (float*)d_out;

    const int n_cells = in_sizes[2];

    static bool attr_set = false;   // attribute setting (not work) — deterministic
    if (!attr_set) {
        cudaFuncSetAttribute(yolo_fused, cudaFuncAttributeMaxDynamicSharedMemorySize, SMEM_DYN);
        attr_set = true;
    }

    int grid = 2 * 148;                       // 2 CTAs/SM @ ~94 KB dynamic smem
    const int n_chunks = n_cells / CHUNK;
    if (grid * WARPS > n_chunks && n_chunks > 0) grid = (n_chunks + WARPS - 1) / WARPS;
    if (grid < 1) grid = 1;
    if (grid > NPART_MAX) grid = NPART_MAX;

    yolo_fused<<<grid, THREADS, SMEM_DYN>>>(pred, target, choice, out, n_cells);
}